// round 1
// baseline (speedup 1.0000x reference)
#include <cuda_runtime.h>
#include <math.h>

// Problem constants
#define NENT   4096
#define ANON   4
#define NTOT   (NENT + ANON)   // 4100
#define DIM    128
#define BATCH  8
#define EPS    1e-10f

// Scratch (no cudaMalloc allowed)
__device__ float g_ew1[NTOT];
__device__ float g_ew2[NTOT];

// ---------------------------------------------------------------------------
// Kernel A: ew1[j] = e_all[j] . w1 ; ew2[j] = e_all[j] . w2
// warp-per-row, float4 loads (row = 512B, 32 lanes x 16B)
// ---------------------------------------------------------------------------
__global__ void __launch_bounds__(256)
compute_ew_kernel(const float* __restrict__ e_table,
                  const float* __restrict__ anon_e,
                  const float* __restrict__ fc_w)
{
    int gwarp = (blockIdx.x * blockDim.x + threadIdx.x) >> 5;
    int lane  = threadIdx.x & 31;
    if (gwarp >= NTOT) return;

    const float* row = (gwarp < NENT)
        ? (e_table + (size_t)gwarp * DIM)
        : (anon_e + (size_t)(gwarp - NENT) * DIM);

    float4 v  = reinterpret_cast<const float4*>(row)[lane];
    float4 w1 = reinterpret_cast<const float4*>(fc_w)[lane];          // fc_w[0, 0:128]
    float4 w2 = reinterpret_cast<const float4*>(fc_w + DIM)[lane];    // fc_w[0, 128:256]

    float s1 = v.x * w1.x + v.y * w1.y + v.z * w1.z + v.w * w1.w;
    float s2 = v.x * w2.x + v.y * w2.y + v.z * w2.z + v.w * w2.w;

    #pragma unroll
    for (int o = 16; o > 0; o >>= 1) {
        s1 += __shfl_down_sync(0xffffffffu, s1, o);
        s2 += __shfl_down_sync(0xffffffffu, s2, o);
    }
    if (lane == 0) {
        g_ew1[gwarp] = s1;
        g_ew2[gwarp] = s2;
    }
}

// ---------------------------------------------------------------------------
// Kernel B: single block.
//   1. 16 warps compute rw1[b] = r_table[x[b,0]] . w1 and
//                       cw1[b] = c_table[x[b,1]] . w1
//   2. ci_max = max_j ew2[j]
//   3. m[b] = max_j sigmoid(ew1[j]+rw1[b]+bias+ci_max) *
//                   sigmoid(ew2[j]+cw1[b]+bias)
//   4. loss = mean_b( -log(1 - m[b] + EPS) )
// ---------------------------------------------------------------------------
#define TPB 512
#define NWARPS (TPB / 32)

__global__ void __launch_bounds__(TPB)
finalize_kernel(const int*   __restrict__ x,
                const float* __restrict__ c_table,
                const float* __restrict__ r_table,
                const float* __restrict__ fc_w,
                const float* __restrict__ fc_b,
                float* __restrict__ out)
{
    __shared__ float s_rw1[BATCH];
    __shared__ float s_cw1[BATCH];
    __shared__ float s_red[TPB];
    __shared__ float s_cimax;
    __shared__ float s_pm[BATCH][NWARPS];

    int tid  = threadIdx.x;
    int warp = tid >> 5;
    int lane = tid & 31;

    // --- gathered dot products (warps 0..7: rw1, warps 8..15: cw1) ---
    {
        int b = warp & 7;
        const float* row = (warp < 8)
            ? (r_table + (size_t)x[2 * b]     * DIM)
            : (c_table + (size_t)x[2 * b + 1] * DIM);
        float4 v  = reinterpret_cast<const float4*>(row)[lane];
        float4 w1 = reinterpret_cast<const float4*>(fc_w)[lane];
        float s = v.x * w1.x + v.y * w1.y + v.z * w1.z + v.w * w1.w;
        #pragma unroll
        for (int o = 16; o > 0; o >>= 1)
            s += __shfl_down_sync(0xffffffffu, s, o);
        if (lane == 0) {
            if (warp < 8) s_rw1[b] = s;
            else          s_cw1[b] = s;
        }
    }

    // --- ci_max = max over g_ew2 ---
    float m = -1e30f;
    for (int j = tid; j < NTOT; j += TPB)
        m = fmaxf(m, g_ew2[j]);
    s_red[tid] = m;
    __syncthreads();
    #pragma unroll
    for (int s = TPB / 2; s > 0; s >>= 1) {
        if (tid < s) s_red[tid] = fmaxf(s_red[tid], s_red[tid + s]);
        __syncthreads();
    }
    if (tid == 0) s_cimax = s_red[0];
    __syncthreads();

    // --- per-batch max of sigmoid product over j ---
    const float bias = fc_b[0];
    const float cim  = s_cimax;

    float aj_base[BATCH];
    float cf_base[BATCH];
    #pragma unroll
    for (int b = 0; b < BATCH; b++) {
        aj_base[b] = s_rw1[b] + bias + cim;   // + ew1[j]  -> r_fs argument (at i*)
        cf_base[b] = s_cw1[b] + bias;         // + ew2[j]  -> c_fs argument
    }

    float pm[BATCH];
    #pragma unroll
    for (int b = 0; b < BATCH; b++) pm[b] = 0.0f;

    for (int j = tid; j < NTOT; j += TPB) {
        float e1 = g_ew1[j];
        float e2 = g_ew2[j];
        #pragma unroll
        for (int b = 0; b < BATCH; b++) {
            float s1 = 1.0f / (1.0f + expf(-(e1 + aj_base[b])));
            float s2 = 1.0f / (1.0f + expf(-(e2 + cf_base[b])));
            pm[b] = fmaxf(pm[b], s1 * s2);
        }
    }

    // --- block max-reduce per batch ---
    #pragma unroll
    for (int b = 0; b < BATCH; b++) {
        float v = pm[b];
        #pragma unroll
        for (int o = 16; o > 0; o >>= 1)
            v = fmaxf(v, __shfl_down_sync(0xffffffffu, v, o));
        if (lane == 0) s_pm[b][warp] = v;
    }
    __syncthreads();

    if (tid == 0) {
        float loss = 0.0f;
        #pragma unroll
        for (int b = 0; b < BATCH; b++) {
            float mb = s_pm[b][0];
            #pragma unroll
            for (int w = 1; w < NWARPS; w++)
                mb = fmaxf(mb, s_pm[b][w]);
            loss += -logf(1.0f - mb + EPS);
        }
        out[0] = loss * (1.0f / (float)BATCH);
    }
}

// ---------------------------------------------------------------------------
// Input order (metadata): x, anon_e_emb, c_table, r_table, e_table, fc_w, fc_b
// ---------------------------------------------------------------------------
extern "C" void kernel_launch(void* const* d_in, const int* in_sizes, int n_in,
                              void* d_out, int out_size)
{
    const int*   x        = (const int*)  d_in[0];
    const float* anon_e   = (const float*)d_in[1];
    const float* c_table  = (const float*)d_in[2];
    const float* r_table  = (const float*)d_in[3];
    const float* e_table  = (const float*)d_in[4];
    const float* fc_w     = (const float*)d_in[5];
    const float* fc_b     = (const float*)d_in[6];
    float*       out      = (float*)d_out;

    // Kernel A: one warp per entity row
    int total_threads = NTOT * 32;
    int blocks = (total_threads + 255) / 256;
    compute_ew_kernel<<<blocks, 256>>>(e_table, anon_e, fc_w);

    // Kernel B: single block finalize
    finalize_kernel<<<1, TPB>>>(x, c_table, r_table, fc_w, fc_b, out);
}

// round 2
// speedup vs baseline: 1.8092x; 1.8092x over previous
#include <cuda_runtime.h>
#include <math.h>

// Problem constants
#define NENT   4096
#define ANON   4
#define NTOT   (NENT + ANON)   // 4100
#define DIM    128
#define BATCH  8
#define EPS    1e-10f

#define TPB    512
#define WPB    (TPB / 32)                      // 16 warps/block
#define NBLK   ((NTOT + WPB - 1) / WPB)        // 257 blocks (warp-per-row)

#define FLT_MAX_BITS 0x7F7FFFFFu

// Scratch (no cudaMalloc allowed). Store exp(-ew1), exp(-ew2).
__device__ float        g_x1[NTOT];
__device__ float        g_x2[NTOT];
__device__ unsigned int g_x2min_bits = FLT_MAX_BITS;  // reset by last block
__device__ unsigned int g_counter    = 0;             // reset by last block

// ---------------------------------------------------------------------------
// Single fused kernel.
// Phase 1 (all blocks): warp-per-row dot products ew1/ew2, store exp(-ew),
//                       block-min of x2 -> global atomicMin (bits).
// Phase 2 (last block): rw1/cw1 gathered dots, then
//   m[b] = 1 / min_j (1 + x1[j]*t1[b]) * (1 + x2[j]*t2[b])
//   where t1[b] = exp(-(rw1[b]+bias)) * min_x2   (min_x2 == exp(-ci_max))
//         t2[b] = exp(-(cw1[b]+bias))
//   loss = mean_b -log(1 - m[b] + EPS)
// ---------------------------------------------------------------------------
__global__ void __launch_bounds__(TPB)
falcon_fused_kernel(const int*   __restrict__ x,
                    const float* __restrict__ anon_e,
                    const float* __restrict__ c_table,
                    const float* __restrict__ r_table,
                    const float* __restrict__ e_table,
                    const float* __restrict__ fc_w,
                    const float* __restrict__ fc_b,
                    float*       __restrict__ out)
{
    __shared__ float        s_wmin[WPB];
    __shared__ unsigned int s_islast;

    int tid  = threadIdx.x;
    int warp = tid >> 5;
    int lane = tid & 31;

    // ---------------- Phase 1: entity dot products + exp ----------------
    int gw = blockIdx.x * WPB + warp;
    float my_x2 = 3.402823466e+38f;  // FLT_MAX

    if (gw < NTOT) {
        const float* row = (gw < NENT)
            ? (e_table + (size_t)gw * DIM)
            : (anon_e + (size_t)(gw - NENT) * DIM);

        float4 v  = reinterpret_cast<const float4*>(row)[lane];
        float4 w1 = reinterpret_cast<const float4*>(fc_w)[lane];        // w[0:128]
        float4 w2 = reinterpret_cast<const float4*>(fc_w + DIM)[lane];  // w[128:256]

        float s1 = v.x * w1.x + v.y * w1.y + v.z * w1.z + v.w * w1.w;
        float s2 = v.x * w2.x + v.y * w2.y + v.z * w2.z + v.w * w2.w;

        #pragma unroll
        for (int o = 16; o > 0; o >>= 1) {
            s1 += __shfl_down_sync(0xffffffffu, s1, o);
            s2 += __shfl_down_sync(0xffffffffu, s2, o);
        }
        if (lane == 0) {
            float x1 = expf(-s1);
            float x2 = expf(-s2);
            g_x1[gw] = x1;
            g_x2[gw] = x2;
            my_x2 = x2;
        }
    }

    // block-min of x2 (positive floats: bit pattern preserves ordering)
    if (lane == 0) s_wmin[warp] = my_x2;
    __syncthreads();
    if (tid == 0) {
        float bm = s_wmin[0];
        #pragma unroll
        for (int w = 1; w < WPB; w++) bm = fminf(bm, s_wmin[w]);
        atomicMin(&g_x2min_bits, __float_as_uint(bm));
        __threadfence();
        unsigned int prev = atomicAdd(&g_counter, 1u);
        s_islast = (prev == NBLK - 1) ? 1u : 0u;
    }
    __syncthreads();

    if (s_islast == 0u) return;

    // ---------------- Phase 2: last block finalizes ----------------
    __threadfence();  // acquire: make all g_x1/g_x2/g_x2min_bits visible

    __shared__ float s_rw1[BATCH];
    __shared__ float s_cw1[BATCH];
    __shared__ float s_dmin[BATCH][WPB];

    // gathered dots: warps 0..7 -> rw1[b], warps 8..15 -> cw1[b]
    {
        int b = warp & 7;
        const float* row = (warp < 8)
            ? (r_table + (size_t)x[2 * b]     * DIM)
            : (c_table + (size_t)x[2 * b + 1] * DIM);
        float4 v  = reinterpret_cast<const float4*>(row)[lane];
        float4 w1 = reinterpret_cast<const float4*>(fc_w)[lane];
        float s = v.x * w1.x + v.y * w1.y + v.z * w1.z + v.w * w1.w;
        #pragma unroll
        for (int o = 16; o > 0; o >>= 1)
            s += __shfl_down_sync(0xffffffffu, s, o);
        if (lane == 0) {
            if (warp < 8) s_rw1[b] = s;
            else          s_cw1[b] = s;
        }
    }
    __syncthreads();

    const float bias   = fc_b[0];
    const float min_x2 = __uint_as_float(g_x2min_bits);  // == exp(-ci_max)

    float t1[BATCH], t2[BATCH];
    #pragma unroll
    for (int b = 0; b < BATCH; b++) {
        t1[b] = expf(-(s_rw1[b] + bias)) * min_x2;
        t2[b] = expf(-(s_cw1[b] + bias));
    }

    // min over j of (1 + x1*t1)*(1 + x2*t2)
    float dmin[BATCH];
    #pragma unroll
    for (int b = 0; b < BATCH; b++) dmin[b] = 3.402823466e+38f;

    for (int j = tid; j < NTOT; j += TPB) {
        float x1 = g_x1[j];
        float x2 = g_x2[j];
        #pragma unroll
        for (int b = 0; b < BATCH; b++) {
            float d1 = fmaf(x1, t1[b], 1.0f);
            float d2 = fmaf(x2, t2[b], 1.0f);
            dmin[b] = fminf(dmin[b], d1 * d2);
        }
    }

    #pragma unroll
    for (int b = 0; b < BATCH; b++) {
        float v = dmin[b];
        #pragma unroll
        for (int o = 16; o > 0; o >>= 1)
            v = fminf(v, __shfl_down_sync(0xffffffffu, v, o));
        if (lane == 0) s_dmin[b][warp] = v;
    }
    __syncthreads();

    if (tid == 0) {
        float loss = 0.0f;
        #pragma unroll
        for (int b = 0; b < BATCH; b++) {
            float dm = s_dmin[b][0];
            #pragma unroll
            for (int w = 1; w < WPB; w++) dm = fminf(dm, s_dmin[b][w]);
            float mb = 1.0f / dm;                 // max_j sigmoid product
            loss += -logf(1.0f - mb + EPS);
        }
        out[0] = loss * (1.0f / (float)BATCH);

        // reset scratch for next graph replay (deterministic)
        g_x2min_bits = FLT_MAX_BITS;
        g_counter    = 0u;
    }
}

// ---------------------------------------------------------------------------
// Input order (metadata): x, anon_e_emb, c_table, r_table, e_table, fc_w, fc_b
// ---------------------------------------------------------------------------
extern "C" void kernel_launch(void* const* d_in, const int* in_sizes, int n_in,
                              void* d_out, int out_size)
{
    const int*   x        = (const int*)  d_in[0];
    const float* anon_e   = (const float*)d_in[1];
    const float* c_table  = (const float*)d_in[2];
    const float* r_table  = (const float*)d_in[3];
    const float* e_table  = (const float*)d_in[4];
    const float* fc_w     = (const float*)d_in[5];
    const float* fc_b     = (const float*)d_in[6];
    float*       out      = (float*)d_out;

    falcon_fused_kernel<<<NBLK, TPB>>>(x, anon_e, c_table, r_table,
                                       e_table, fc_w, fc_b, out);
}